// round 5
// baseline (speedup 1.0000x reference)
#include <cuda_runtime.h>
#include <math.h>
#include <stdint.h>

// Problem constants (fixed by reference)
#define BB 256
#define TT 72
#define NN 5
#define FF_IN 10
#define HH 4
#define CC 32
#define DD 128
#define FFD 256
#define NHEAD 4
#define DHEAD 32
#define BT (BB*TT)   // 18432

// ---------------- device scratch (no allocations allowed) ----------------
__device__ float d_z[BT*DD];
__device__ float d_qkv[BT*3*DD];
__device__ float d_o[BT*DD];
__device__ float d_ff[BT*FFD];
__device__ float d_Anorm[NN*NN];
__device__ int   d_src2[64];
__device__ int   d_dst2[64];

// ---------------- tf32 / f32x2 helpers ----------------
__device__ __forceinline__ uint32_t to_tf32(float x) {
    uint32_t r;
    asm("cvt.rna.tf32.f32 %0, %1;" : "=r"(r) : "f"(x));
    return r;
}
__device__ __forceinline__ void mma_tf32(float* d, const uint32_t* a, const uint32_t* b) {
    asm volatile(
        "mma.sync.aligned.m16n8k8.row.col.f32.tf32.tf32.f32 "
        "{%0,%1,%2,%3}, {%4,%5,%6,%7}, {%8,%9}, {%0,%1,%2,%3};"
        : "+f"(d[0]), "+f"(d[1]), "+f"(d[2]), "+f"(d[3])
        : "r"(a[0]), "r"(a[1]), "r"(a[2]), "r"(a[3]), "r"(b[0]), "r"(b[1]));
}
__device__ __forceinline__ unsigned long long pk2(float x, float y) {
    unsigned long long r;
    asm("mov.b64 %0, {%1, %2};" : "=l"(r) : "f"(x), "f"(y));
    return r;
}
__device__ __forceinline__ void fma2(unsigned long long &acc, unsigned long long a, unsigned long long b) {
    asm("fma.rn.f32x2 %0, %1, %2, %0;" : "+l"(acc) : "l"(a), "l"(b));
}
__device__ __forceinline__ void upk2(unsigned long long v, float &x, float &y) {
    asm("mov.b64 {%0, %1}, %2;" : "=f"(x), "=f"(y) : "l"(v));
}

// ---------------- graph build (single thread, trivial) ----------------
__global__ void build_graph_kernel(const int* __restrict__ ei, int E) {
    if (threadIdx.x != 0 || blockIdx.x != 0) return;
    float A[NN][NN];
    for (int i = 0; i < NN*NN; i++) ((float*)A)[i] = 0.f;
    for (int e = 0; e < E; e++) {
        int s = ei[e];
        int d = ei[E + e];
        A[d][s] += 1.f;
        d_src2[e] = s; d_dst2[e] = d;
    }
    for (int n = 0; n < NN; n++) {
        A[n][n] += 1.f;
        d_src2[E + n] = n; d_dst2[E + n] = n;
    }
    float dinv[NN];
    for (int n = 0; n < NN; n++) {
        float s = 0.f;
        for (int j = 0; j < NN; j++) s += A[n][j];
        dinv[n] = (s > 0.f) ? (1.f / sqrtf(s)) : 0.f;
    }
    for (int i = 0; i < NN; i++)
        for (int j = 0; j < NN; j++)
            d_Anorm[i*NN + j] = dinv[i] * A[i][j] * dinv[j];
}

// ---------------- fused dual block reduce (128 threads) ----------------
__device__ __forceinline__ void blockReduceSum2_128(float &a, float &b, float* sred) {
    __syncthreads();
    #pragma unroll
    for (int o = 16; o > 0; o >>= 1) {
        a += __shfl_xor_sync(0xffffffffu, a, o);
        b += __shfl_xor_sync(0xffffffffu, b, o);
    }
    if ((threadIdx.x & 31) == 0) {
        int w = threadIdx.x >> 5;
        sred[w] = a; sred[4 + w] = b;
    }
    __syncthreads();
    a = sred[0] + sred[1] + sred[2] + sred[3];
    b = sred[4] + sred[5] + sred[6] + sred[7];
}

// ---------------- fused GCN + GAT + LN + node-mean + PE ----------------
__global__ void gcn_gat_kernel(
    const float* __restrict__ x,
    const float* __restrict__ gcn_w, const float* __restrict__ gcn_b,
    const float* __restrict__ gat_w, const float* __restrict__ a_src,
    const float* __restrict__ a_dst, const float* __restrict__ gat_b,
    const float* __restrict__ gln_g, const float* __restrict__ gln_b,
    float* __restrict__ z, int E2)
{
    int bt = blockIdx.x;
    int tid = threadIdx.x;  // 128

    __shared__ float sx[NN][FF_IN];
    __shared__ float sxw[NN][64];
    __shared__ float sgcn[NN][64];
    __shared__ float sh[NN][DD];
    __shared__ float sagg[NN][DD];
    __shared__ float sas[NN][HH], sad[NN][HH];
    __shared__ float se[32][HH];
    __shared__ float salpha[32][HH];
    __shared__ float smx[NN][HH], sden[NN][HH];
    __shared__ float sAn[NN*NN];
    __shared__ int   ssrc[32], sdst[32];
    __shared__ float sred[8];

    const float* xp = x + (size_t)bt * NN * FF_IN;
    if (tid < NN*FF_IN) ((float*)sx)[tid] = xp[tid];
    if (tid < NN*NN) sAn[tid] = d_Anorm[tid];
    if (tid < E2) { ssrc[tid] = d_src2[tid]; sdst[tid] = d_dst2[tid]; }
    __syncthreads();

    for (int idx = tid; idx < NN*64; idx += 128) {
        int n = idx >> 6, c = idx & 63;
        float acc = gcn_b[c];
        #pragma unroll
        for (int f = 0; f < FF_IN; f++) acc += sx[n][f] * gcn_w[f*64 + c];
        sxw[n][c] = acc;
    }
    __syncthreads();

    for (int idx = tid; idx < NN*64; idx += 128) {
        int n = idx >> 6, c = idx & 63;
        float acc = 0.f;
        #pragma unroll
        for (int m = 0; m < NN; m++) acc += sAn[n*NN + m] * sxw[m][c];
        sgcn[n][c] = tanhf(acc);
    }
    __syncthreads();

    for (int idx = tid; idx < NN*DD; idx += 128) {
        int n = idx >> 7, d = idx & 127;
        float acc = 0.f;
        #pragma unroll 8
        for (int f = 0; f < 64; f++) acc += sgcn[n][f] * gat_w[f*DD + d];
        sh[n][d] = acc;
    }
    __syncthreads();

    if (tid < NN*HH*2) {
        int n = tid / (HH*2), r = tid % (HH*2), hd = r >> 1, which = r & 1;
        const float* av = which ? a_dst : a_src;
        float acc = 0.f;
        #pragma unroll
        for (int c = 0; c < CC; c++) acc += sh[n][hd*CC + c] * av[hd*CC + c];
        if (which) sad[n][hd] = acc; else sas[n][hd] = acc;
    }
    __syncthreads();

    for (int idx = tid; idx < E2*HH; idx += 128) {
        int e = idx >> 2, hd = idx & 3;
        float v = sas[ssrc[e]][hd] + sad[sdst[e]][hd];
        se[e][hd] = (v > 0.f) ? v : 0.2f * v;
    }
    __syncthreads();

    if (tid < NN*HH) {
        int n = tid >> 2, hd = tid & 3;
        float m = -1e30f;
        for (int e = 0; e < E2; e++) if (sdst[e] == n) m = fmaxf(m, se[e][hd]);
        float s = 0.f;
        for (int e = 0; e < E2; e++) if (sdst[e] == n) s += __expf(se[e][hd] - m);
        smx[n][hd] = m; sden[n][hd] = s;
    }
    __syncthreads();

    for (int idx = tid; idx < E2*HH; idx += 128) {
        int e = idx >> 2, hd = idx & 3;
        int n = sdst[e];
        salpha[e][hd] = __expf(se[e][hd] - smx[n][hd]) / sden[n][hd];
    }
    __syncthreads();

    for (int idx = tid; idx < NN*DD; idx += 128) {
        int n = idx >> 7, d = idx & 127;
        int hd = d >> 5;
        float acc = 0.f;
        for (int e = 0; e < E2; e++) {
            if (sdst[e] == n)
                acc += salpha[e][hd] * sh[ssrc[e]][d];
        }
        sagg[n][d] = acc + gat_b[d];
    }

    int d = tid;
    float gv = gln_g[d], bv = gln_b[d];
    float zacc = 0.f;
    for (int n = 0; n < NN; n++) {
        float v = sagg[n][d];
        float s1 = v, s2 = v * v;
        blockReduceSum2_128(s1, s2, sred);
        float mu = s1 * (1.f / DD);
        float var = s2 * (1.f / DD) - mu * mu;
        zacc += (v - mu) * rsqrtf(var + 1e-5f) * gv + bv;
    }
    zacc *= (1.f / NN);

    int t = bt % TT;
    float arg = (float)t * __expf(-(float)((d >> 1) << 1) * (logf(10000.f) / (float)DD));
    zacc += (d & 1) ? cosf(arg) : sinf(arg);
    z[(size_t)bt * DD + d] = zacc;
}

// ---------------- tf32 tensor-core GEMM with global prefetch ----------------
// C = A(MxK) @ B(KxN) + bias. 128x128 block tile, 8 warps (2x4), 64x32 warp tile,
// m16n8k8 tf32 mma, K-step 16, smem stride 136 (conflict-free fragment loads).
// EPI: 0 = bias, 1 = bias+relu, 2 = bias + residual + LayerNorm (N==128 only).
#define TFS 136
template<int EPI>
__global__ void __launch_bounds__(256)
gemm_tf32(const float* __restrict__ A, const float* __restrict__ Bm,
          const float* __restrict__ bias, float* __restrict__ Cm,
          const float* __restrict__ resid,
          const float* __restrict__ ln_g, const float* __restrict__ ln_b,
          int M, int N, int K)
{
    extern __shared__ char smem_raw[];
    uint32_t* As = (uint32_t*)smem_raw;          // [16][TFS]
    uint32_t* Bs = As + 16*TFS;                  // [16][TFS]

    int tid = threadIdx.x;
    int warp = tid >> 5, lane = tid & 31;
    int tig = lane & 3, grp = lane >> 2;
    int wm = warp >> 2, wn = warp & 3;           // 2 x 4 warps
    int m0 = blockIdx.y * 128, n0 = blockIdx.x * 128;

    float acc[4][4][4];
    #pragma unroll
    for (int i = 0; i < 4; i++)
        #pragma unroll
        for (int j = 0; j < 4; j++)
            #pragma unroll
            for (int c = 0; c < 4; c++) acc[i][j][c] = 0.f;

    // per-thread staging coordinates
    int fa0 = tid, fa1 = tid + 256;
    int a_m0 = fa0 >> 2, a_k0 = (fa0 & 3) * 4;
    int a_m1 = fa1 >> 2, a_k1 = (fa1 & 3) * 4;
    int b_k0 = fa0 >> 5, b_n0 = (fa0 & 31) * 4;
    int b_k1 = fa1 >> 5, b_n1 = (fa1 & 31) * 4;

    int nk = K >> 4;
    float4 af[2], bf[2];
    af[0] = *(const float4*)&A[(size_t)(m0 + a_m0)*K + a_k0];
    af[1] = *(const float4*)&A[(size_t)(m0 + a_m1)*K + a_k1];
    bf[0] = *(const float4*)&Bm[(size_t)b_k0*N + n0 + b_n0];
    bf[1] = *(const float4*)&Bm[(size_t)b_k1*N + n0 + b_n1];

    for (int kt = 0; kt < nk; kt++) {
        // stage current tile (convert to tf32)
        As[(a_k0 + 0)*TFS + a_m0] = to_tf32(af[0].x);
        As[(a_k0 + 1)*TFS + a_m0] = to_tf32(af[0].y);
        As[(a_k0 + 2)*TFS + a_m0] = to_tf32(af[0].z);
        As[(a_k0 + 3)*TFS + a_m0] = to_tf32(af[0].w);
        As[(a_k1 + 0)*TFS + a_m1] = to_tf32(af[1].x);
        As[(a_k1 + 1)*TFS + a_m1] = to_tf32(af[1].y);
        As[(a_k1 + 2)*TFS + a_m1] = to_tf32(af[1].z);
        As[(a_k1 + 3)*TFS + a_m1] = to_tf32(af[1].w);
        uint32_t* p0 = &Bs[b_k0*TFS + b_n0];
        p0[0] = to_tf32(bf[0].x); p0[1] = to_tf32(bf[0].y);
        p0[2] = to_tf32(bf[0].z); p0[3] = to_tf32(bf[0].w);
        uint32_t* p1 = &Bs[b_k1*TFS + b_n1];
        p1[0] = to_tf32(bf[1].x); p1[1] = to_tf32(bf[1].y);
        p1[2] = to_tf32(bf[1].z); p1[3] = to_tf32(bf[1].w);
        __syncthreads();

        // prefetch next tile into registers (overlaps with MMAs below)
        if (kt + 1 < nk) {
            int k0 = (kt + 1) * 16;
            af[0] = *(const float4*)&A[(size_t)(m0 + a_m0)*K + k0 + a_k0];
            af[1] = *(const float4*)&A[(size_t)(m0 + a_m1)*K + k0 + a_k1];
            bf[0] = *(const float4*)&Bm[(size_t)(k0 + b_k0)*N + n0 + b_n0];
            bf[1] = *(const float4*)&Bm[(size_t)(k0 + b_k1)*N + n0 + b_n1];
        }

        #pragma unroll
        for (int ks = 0; ks < 2; ks++) {
            int kb = ks*8;
            uint32_t afr[4][4];
            #pragma unroll
            for (int mf = 0; mf < 4; mf++) {
                int r0 = wm*64 + mf*16 + grp;
                afr[mf][0] = As[(kb + tig)*TFS + r0];
                afr[mf][1] = As[(kb + tig)*TFS + r0 + 8];
                afr[mf][2] = As[(kb + tig + 4)*TFS + r0];
                afr[mf][3] = As[(kb + tig + 4)*TFS + r0 + 8];
            }
            uint32_t bfr[4][2];
            #pragma unroll
            for (int nf = 0; nf < 4; nf++) {
                int c0 = wn*32 + nf*8 + grp;
                bfr[nf][0] = Bs[(kb + tig)*TFS + c0];
                bfr[nf][1] = Bs[(kb + tig + 4)*TFS + c0];
            }
            #pragma unroll
            for (int mf = 0; mf < 4; mf++)
                #pragma unroll
                for (int nf = 0; nf < 4; nf++)
                    mma_tf32(acc[mf][nf], afr[mf], bfr[nf]);
        }
        __syncthreads();
    }

    if (EPI == 2) {
        // Stage C into smem [128][132], then row-wise residual+LN (N==128, n0==0).
        float* Cs = (float*)smem_raw;            // [128][132]
        #pragma unroll
        for (int mf = 0; mf < 4; mf++) {
            int r = wm*64 + mf*16 + grp;
            #pragma unroll
            for (int nf = 0; nf < 4; nf++) {
                int c = wn*32 + nf*8 + 2*tig;
                Cs[r*132 + c]           = acc[mf][nf][0];
                Cs[r*132 + c + 1]       = acc[mf][nf][1];
                Cs[(r + 8)*132 + c]     = acc[mf][nf][2];
                Cs[(r + 8)*132 + c + 1] = acc[mf][nf][3];
            }
        }
        __syncthreads();

        float4 bb = *(const float4*)&bias[lane*4];
        float4 gg = *(const float4*)&ln_g[lane*4];
        float4 be = *(const float4*)&ln_b[lane*4];
        for (int r = warp*16; r < warp*16 + 16; r++) {
            int m = m0 + r;
            float4 cv = *(const float4*)&Cs[r*132 + lane*4];
            float4 zv = *(const float4*)&resid[(size_t)m*128 + lane*4];
            float v[4] = {cv.x + bb.x + zv.x, cv.y + bb.y + zv.y,
                          cv.z + bb.z + zv.z, cv.w + bb.w + zv.w};
            float s = v[0] + v[1] + v[2] + v[3];
            #pragma unroll
            for (int o = 16; o > 0; o >>= 1) s += __shfl_xor_sync(0xffffffffu, s, o);
            float mu = s * (1.f / 128.f);
            float q = 0.f;
            #pragma unroll
            for (int j = 0; j < 4; j++) { float dv = v[j] - mu; q += dv * dv; }
            #pragma unroll
            for (int o = 16; o > 0; o >>= 1) q += __shfl_xor_sync(0xffffffffu, q, o);
            float rstd = rsqrtf(q * (1.f / 128.f) + 1e-5f);
            float4 rv;
            rv.x = (v[0] - mu) * rstd * gg.x + be.x;
            rv.y = (v[1] - mu) * rstd * gg.y + be.y;
            rv.z = (v[2] - mu) * rstd * gg.z + be.z;
            rv.w = (v[3] - mu) * rstd * gg.w + be.w;
            *(float4*)&Cm[(size_t)m*128 + lane*4] = rv;
        }
    } else {
        #pragma unroll
        for (int mf = 0; mf < 4; mf++) {
            int r = m0 + wm*64 + mf*16 + grp;
            #pragma unroll
            for (int nf = 0; nf < 4; nf++) {
                int c = n0 + wn*32 + nf*8 + 2*tig;
                float b0 = bias[c], b1 = bias[c + 1];
                float v0 = acc[mf][nf][0] + b0;
                float v1 = acc[mf][nf][1] + b1;
                float v2 = acc[mf][nf][2] + b0;
                float v3 = acc[mf][nf][3] + b1;
                if (EPI == 1) {
                    v0 = fmaxf(v0, 0.f); v1 = fmaxf(v1, 0.f);
                    v2 = fmaxf(v2, 0.f); v3 = fmaxf(v3, 0.f);
                }
                *(float2*)&Cm[(size_t)r*N + c]       = make_float2(v0, v1);
                *(float2*)&Cm[(size_t)(r + 8)*N + c] = make_float2(v2, v3);
            }
        }
    }
}

// ---------------- attention per (b, head): f32x2, balanced, V-load overlap ----
#define QKS 36
#define SSS 76
__global__ void __launch_bounds__(256, 4)
attn_kernel(const float* __restrict__ qkv, float* __restrict__ obuf)
{
    int b = blockIdx.x;
    int h = blockIdx.y;
    int tid = threadIdx.x;  // 256

    __shared__ float sq[TT*QKS];    // Q during S; V afterwards
    __shared__ float sk[TT*QKS];    // K
    __shared__ float sS[TT*SSS];

    const float* base = qkv + (size_t)b * TT * (3*DD) + h*DHEAD;
    for (int idx = tid; idx < TT*DHEAD; idx += 256) {
        int t = idx >> 5, d = idx & 31;
        sq[t*QKS + d] = base[t*(3*DD)      + d];
        sk[t*QKS + d] = base[t*(3*DD) + DD + d];
    }
    __syncthreads();

    const float inv_scale = rsqrtf((float)DHEAD);
    // S = Q @ K^T * inv_scale : 4x4 tiles, packed f32x2 accumulation
    for (int tt = tid; tt < 324; tt += 256) {
        int i0 = (tt / 18) * 4, j0 = (tt % 18) * 4;
        unsigned long long acc2[4][4];
        #pragma unroll
        for (int a = 0; a < 4; a++)
            #pragma unroll
            for (int c = 0; c < 4; c++) acc2[a][c] = 0ULL;
        #pragma unroll
        for (int d4 = 0; d4 < DHEAD; d4 += 4) {
            ulonglong2 q[4], k[4];
            #pragma unroll
            for (int a = 0; a < 4; a++) q[a] = *(const ulonglong2*)&sq[(i0+a)*QKS + d4];
            #pragma unroll
            for (int c = 0; c < 4; c++) k[c] = *(const ulonglong2*)&sk[(j0+c)*QKS + d4];
            #pragma unroll
            for (int a = 0; a < 4; a++)
                #pragma unroll
                for (int c = 0; c < 4; c++) {
                    fma2(acc2[a][c], q[a].x, k[c].x);
                    fma2(acc2[a][c], q[a].y, k[c].y);
                }
        }
        #pragma unroll
        for (int a = 0; a < 4; a++)
            #pragma unroll
            for (int c = 0; c < 4; c++) {
                float lo, hi;
                upk2(acc2[a][c], lo, hi);
                sS[(i0+a)*SSS + j0 + c] = (lo + hi) * inv_scale;
            }
    }
    __syncthreads();

    // Load V into sq (Q dead) — overlaps with softmax below (same sync window)
    for (int idx = tid; idx < TT*DHEAD; idx += 256) {
        int t = idx >> 5, d = idx & 31;
        sq[t*QKS + d] = base[t*(3*DD) + 2*DD + d];
    }

    // rowwise softmax: warp per row, 8 warps
    int wid = tid >> 5, lane = tid & 31;
    for (int i = wid; i < TT; i += 8) {
        float m = -1e30f;
        for (int j = lane; j < TT; j += 32) m = fmaxf(m, sS[i*SSS + j]);
        #pragma unroll
        for (int o = 16; o > 0; o >>= 1) m = fmaxf(m, __shfl_xor_sync(0xffffffffu, m, o));
        float s = 0.f;
        for (int j = lane; j < TT; j += 32) {
            float e = __expf(sS[i*SSS + j] - m);
            sS[i*SSS + j] = e;
            s += e;
        }
        #pragma unroll
        for (int o = 16; o > 0; o >>= 1) s += __shfl_xor_sync(0xffffffffu, s, o);
        float inv = 1.f / s;
        for (int j = lane; j < TT; j += 32) sS[i*SSS + j] *= inv;
    }
    __syncthreads();

    // O = S @ V : 288 (1 row x 8 col) tiles, packed f32x2, all threads active
    for (int tt = tid; tt < 288; tt += 256) {
        int i = tt >> 2;
        int d0 = (tt & 3) * 8;
        unsigned long long acc2[4];
        #pragma unroll
        for (int c = 0; c < 4; c++) acc2[c] = 0ULL;
        for (int j = 0; j < TT; j++) {
            float s = sS[i*SSS + j];
            unsigned long long ss = pk2(s, s);
            ulonglong2 v0 = *(const ulonglong2*)&sq[j*QKS + d0];
            ulonglong2 v1 = *(const ulonglong2*)&sq[j*QKS + d0 + 4];
            fma2(acc2[0], ss, v0.x);
            fma2(acc2[1], ss, v0.y);
            fma2(acc2[2], ss, v1.x);
            fma2(acc2[3], ss, v1.y);
        }
        float r[8];
        upk2(acc2[0], r[0], r[1]);
        upk2(acc2[1], r[2], r[3]);
        upk2(acc2[2], r[4], r[5]);
        upk2(acc2[3], r[6], r[7]);
        float* o = &obuf[((size_t)b*TT + i)*DD + h*DHEAD + d0];
        *(float4*)o       = make_float4(r[0], r[1], r[2], r[3]);
        *(float4*)(o + 4) = make_float4(r[4], r[5], r[6], r[7]);
    }
}

// ---------------- 6 MLP heads on last timestep ----------------
__global__ void heads_kernel(const float* __restrict__ z,
                             const float* __restrict__ hw1, const float* __restrict__ hb1,
                             const float* __restrict__ hw2, const float* __restrict__ hb2,
                             float* __restrict__ out)
{
    int b = blockIdx.x;
    int k = blockIdx.y;
    int tid = threadIdx.x;  // 64
    __shared__ float slast[DD];
    __shared__ float sh1[64];
    const float* zr = z + ((size_t)b*TT + (TT-1))*DD;
    slast[tid] = zr[tid];
    slast[tid + 64] = zr[tid + 64];
    __syncthreads();

    float acc = hb1[k*64 + tid];
    const float* w1 = hw1 + (size_t)k*DD*64;
    #pragma unroll 8
    for (int d = 0; d < DD; d++) acc += slast[d] * w1[d*64 + tid];
    sh1[tid] = fmaxf(acc, 0.f);
    __syncthreads();

    if (tid < 5) {
        float a2 = hb2[k*5 + tid];
        const float* w2 = hw2 + (size_t)k*64*5;
        #pragma unroll 8
        for (int m = 0; m < 64; m++) a2 += sh1[m] * w2[m*5 + tid];
        out[((size_t)k*BB + b)*5 + tid] = a2;
    }
}

// ---------------- launcher ----------------
extern "C" void kernel_launch(void* const* d_in, const int* in_sizes, int n_in,
                              void* d_out, int out_size)
{
    const float* x        = (const float*)d_in[0];
    const int*   ei       = (const int*)  d_in[1];
    const float* gcn_w    = (const float*)d_in[2];
    const float* gcn_b    = (const float*)d_in[3];
    const float* gat_w    = (const float*)d_in[4];
    const float* gat_a_s  = (const float*)d_in[5];
    const float* gat_a_d  = (const float*)d_in[6];
    const float* gat_b    = (const float*)d_in[7];
    const float* gln_g    = (const float*)d_in[8];
    const float* gln_b    = (const float*)d_in[9];
    const float* tw_qkv   = (const float*)d_in[10];
    const float* tb_qkv   = (const float*)d_in[11];
    const float* tw_o     = (const float*)d_in[12];
    const float* tb_o     = (const float*)d_in[13];
    const float* ln1_g    = (const float*)d_in[14];
    const float* ln1_b    = (const float*)d_in[15];
    const float* w_ff1    = (const float*)d_in[16];
    const float* b_ff1    = (const float*)d_in[17];
    const float* w_ff2    = (const float*)d_in[18];
    const float* b_ff2    = (const float*)d_in[19];
    const float* ln2_g    = (const float*)d_in[20];
    const float* ln2_b    = (const float*)d_in[21];
    const float* hw1      = (const float*)d_in[22];
    const float* hb1      = (const float*)d_in[23];
    const float* hw2      = (const float*)d_in[24];
    const float* hb2      = (const float*)d_in[25];
    float* out = (float*)d_out;

    float *zp, *qkvp, *op, *ffp;
    cudaGetSymbolAddress((void**)&zp,   d_z);
    cudaGetSymbolAddress((void**)&qkvp, d_qkv);
    cudaGetSymbolAddress((void**)&op,   d_o);
    cudaGetSymbolAddress((void**)&ffp,  d_ff);

    const int SMEM_MAIN = 2 * 16 * TFS * 4;       // 17408 B
    const int SMEM_EPI2 = 128 * 132 * 4;          // 67584 B
    cudaFuncSetAttribute(gemm_tf32<2>, cudaFuncAttributeMaxDynamicSharedMemorySize, SMEM_EPI2);

    int E = in_sizes[1] / 2;

    build_graph_kernel<<<1, 32>>>(ei, E);

    gcn_gat_kernel<<<BT, 128>>>(x, gcn_w, gcn_b, gat_w, gat_a_s, gat_a_d,
                                gat_b, gln_g, gln_b, zp, E + NN);

    for (int i = 0; i < 3; i++) {
        // qkv = z @ Wqkv + b      (18432 x 384, K=128)
        gemm_tf32<0><<<dim3((3*DD)/128, BT/128), 256, SMEM_MAIN>>>(
            zp, tw_qkv + (size_t)i*DD*3*DD, tb_qkv + (size_t)i*3*DD, qkvp,
            nullptr, nullptr, nullptr, BT, 3*DD, DD);
        // attention
        attn_kernel<<<dim3(BB, NHEAD), 256>>>(qkvp, op);
        // z = LN(z + o @ Wo + b)  — fused epilogue
        gemm_tf32<2><<<dim3(1, BT/128), 256, SMEM_EPI2>>>(
            op, tw_o + (size_t)i*DD*DD, tb_o + (size_t)i*DD, zp,
            zp, ln1_g + (size_t)i*DD, ln1_b + (size_t)i*DD, BT, DD, DD);
        // ff1 = relu(z @ W1 + b1)
        gemm_tf32<1><<<dim3(FFD/128, BT/128), 256, SMEM_MAIN>>>(
            zp, w_ff1 + (size_t)i*DD*FFD, b_ff1 + (size_t)i*FFD, ffp,
            nullptr, nullptr, nullptr, BT, FFD, DD);
        // z = LN(z + ff1 @ W2 + b2) — fused epilogue (K=256)
        gemm_tf32<2><<<dim3(1, BT/128), 256, SMEM_EPI2>>>(
            ffp, w_ff2 + (size_t)i*FFD*DD, b_ff2 + (size_t)i*DD, zp,
            zp, ln2_g + (size_t)i*DD, ln2_b + (size_t)i*DD, BT, DD, FFD);
    }

    heads_kernel<<<dim3(BB, 6), 64>>>(zp, hw1, hb1, hw2, hb2, out);
}

// round 6
// speedup vs baseline: 1.5236x; 1.5236x over previous
#include <cuda_runtime.h>
#include <math.h>
#include <stdint.h>

// Problem constants (fixed by reference)
#define BB 256
#define TT 72
#define NN 5
#define FF_IN 10
#define HH 4
#define CC 32
#define DD 128
#define FFD 256
#define NHEAD 4
#define DHEAD 32
#define BT (BB*TT)   // 18432

// ---------------- device scratch (no allocations allowed) ----------------
__device__ float d_z[BT*DD];
__device__ float d_qkv[BT*3*DD];
__device__ float d_o[BT*DD];
__device__ float d_ff[BT*FFD];
__device__ float d_Anorm[NN*NN];
__device__ int   d_src2[64];
__device__ int   d_dst2[64];

// ---------------- tf32 helpers ----------------
__device__ __forceinline__ uint32_t to_tf32(float x) {
    uint32_t r;
    asm("cvt.rna.tf32.f32 %0, %1;" : "=r"(r) : "f"(x));
    return r;
}
__device__ __forceinline__ void mma_tf32(float* d, const uint32_t* a, const uint32_t* b) {
    asm volatile(
        "mma.sync.aligned.m16n8k8.row.col.f32.tf32.tf32.f32 "
        "{%0,%1,%2,%3}, {%4,%5,%6,%7}, {%8,%9}, {%0,%1,%2,%3};"
        : "+f"(d[0]), "+f"(d[1]), "+f"(d[2]), "+f"(d[3])
        : "r"(a[0]), "r"(a[1]), "r"(a[2]), "r"(a[3]), "r"(b[0]), "r"(b[1]));
}

// ---------------- graph build (single thread, trivial) ----------------
__global__ void build_graph_kernel(const int* __restrict__ ei, int E) {
    if (threadIdx.x != 0 || blockIdx.x != 0) return;
    float A[NN][NN];
    for (int i = 0; i < NN*NN; i++) ((float*)A)[i] = 0.f;
    for (int e = 0; e < E; e++) {
        int s = ei[e];
        int d = ei[E + e];
        A[d][s] += 1.f;
        d_src2[e] = s; d_dst2[e] = d;
    }
    for (int n = 0; n < NN; n++) {
        A[n][n] += 1.f;
        d_src2[E + n] = n; d_dst2[E + n] = n;
    }
    float dinv[NN];
    for (int n = 0; n < NN; n++) {
        float s = 0.f;
        for (int j = 0; j < NN; j++) s += A[n][j];
        dinv[n] = (s > 0.f) ? (1.f / sqrtf(s)) : 0.f;
    }
    for (int i = 0; i < NN; i++)
        for (int j = 0; j < NN; j++)
            d_Anorm[i*NN + j] = dinv[i] * A[i][j] * dinv[j];
}

// ---------------- fused dual block reduce (128 threads) ----------------
__device__ __forceinline__ void blockReduceSum2_128(float &a, float &b, float* sred) {
    __syncthreads();
    #pragma unroll
    for (int o = 16; o > 0; o >>= 1) {
        a += __shfl_xor_sync(0xffffffffu, a, o);
        b += __shfl_xor_sync(0xffffffffu, b, o);
    }
    if ((threadIdx.x & 31) == 0) {
        int w = threadIdx.x >> 5;
        sred[w] = a; sred[4 + w] = b;
    }
    __syncthreads();
    a = sred[0] + sred[1] + sred[2] + sred[3];
    b = sred[4] + sred[5] + sred[6] + sred[7];
}

// ---------------- fused GCN + GAT + LN + node-mean + PE ----------------
__global__ void gcn_gat_kernel(
    const float* __restrict__ x,
    const float* __restrict__ gcn_w, const float* __restrict__ gcn_b,
    const float* __restrict__ gat_w, const float* __restrict__ a_src,
    const float* __restrict__ a_dst, const float* __restrict__ gat_b,
    const float* __restrict__ gln_g, const float* __restrict__ gln_b,
    float* __restrict__ z, int E2)
{
    int bt = blockIdx.x;
    int tid = threadIdx.x;  // 128

    __shared__ float sx[NN][FF_IN];
    __shared__ float sxw[NN][64];
    __shared__ float sgcn[NN][64];
    __shared__ float sh[NN][DD];
    __shared__ float sagg[NN][DD];
    __shared__ float sas[NN][HH], sad[NN][HH];
    __shared__ float se[32][HH];
    __shared__ float salpha[32][HH];
    __shared__ float smx[NN][HH], sden[NN][HH];
    __shared__ float sAn[NN*NN];
    __shared__ int   ssrc[32], sdst[32];
    __shared__ float sred[8];

    const float* xp = x + (size_t)bt * NN * FF_IN;
    if (tid < NN*FF_IN) ((float*)sx)[tid] = xp[tid];
    if (tid < NN*NN) sAn[tid] = d_Anorm[tid];
    if (tid < E2) { ssrc[tid] = d_src2[tid]; sdst[tid] = d_dst2[tid]; }
    __syncthreads();

    for (int idx = tid; idx < NN*64; idx += 128) {
        int n = idx >> 6, c = idx & 63;
        float acc = gcn_b[c];
        #pragma unroll
        for (int f = 0; f < FF_IN; f++) acc += sx[n][f] * gcn_w[f*64 + c];
        sxw[n][c] = acc;
    }
    __syncthreads();

    for (int idx = tid; idx < NN*64; idx += 128) {
        int n = idx >> 6, c = idx & 63;
        float acc = 0.f;
        #pragma unroll
        for (int m = 0; m < NN; m++) acc += sAn[n*NN + m] * sxw[m][c];
        sgcn[n][c] = tanhf(acc);
    }
    __syncthreads();

    for (int idx = tid; idx < NN*DD; idx += 128) {
        int n = idx >> 7, d = idx & 127;
        float acc = 0.f;
        #pragma unroll 8
        for (int f = 0; f < 64; f++) acc += sgcn[n][f] * gat_w[f*DD + d];
        sh[n][d] = acc;
    }
    __syncthreads();

    if (tid < NN*HH*2) {
        int n = tid / (HH*2), r = tid % (HH*2), hd = r >> 1, which = r & 1;
        const float* av = which ? a_dst : a_src;
        float acc = 0.f;
        #pragma unroll
        for (int c = 0; c < CC; c++) acc += sh[n][hd*CC + c] * av[hd*CC + c];
        if (which) sad[n][hd] = acc; else sas[n][hd] = acc;
    }
    __syncthreads();

    for (int idx = tid; idx < E2*HH; idx += 128) {
        int e = idx >> 2, hd = idx & 3;
        float v = sas[ssrc[e]][hd] + sad[sdst[e]][hd];
        se[e][hd] = (v > 0.f) ? v : 0.2f * v;
    }
    __syncthreads();

    if (tid < NN*HH) {
        int n = tid >> 2, hd = tid & 3;
        float m = -1e30f;
        for (int e = 0; e < E2; e++) if (sdst[e] == n) m = fmaxf(m, se[e][hd]);
        float s = 0.f;
        for (int e = 0; e < E2; e++) if (sdst[e] == n) s += __expf(se[e][hd] - m);
        smx[n][hd] = m; sden[n][hd] = s;
    }
    __syncthreads();

    for (int idx = tid; idx < E2*HH; idx += 128) {
        int e = idx >> 2, hd = idx & 3;
        int n = sdst[e];
        salpha[e][hd] = __expf(se[e][hd] - smx[n][hd]) / sden[n][hd];
    }
    __syncthreads();

    for (int idx = tid; idx < NN*DD; idx += 128) {
        int n = idx >> 7, d = idx & 127;
        int hd = d >> 5;
        float acc = 0.f;
        for (int e = 0; e < E2; e++) {
            if (sdst[e] == n)
                acc += salpha[e][hd] * sh[ssrc[e]][d];
        }
        sagg[n][d] = acc + gat_b[d];
    }

    int d = tid;
    float gv = gln_g[d], bv = gln_b[d];
    float zacc = 0.f;
    for (int n = 0; n < NN; n++) {
        float v = sagg[n][d];
        float s1 = v, s2 = v * v;
        blockReduceSum2_128(s1, s2, sred);
        float mu = s1 * (1.f / DD);
        float var = s2 * (1.f / DD) - mu * mu;
        zacc += (v - mu) * rsqrtf(var + 1e-5f) * gv + bv;
    }
    zacc *= (1.f / NN);

    int t = bt % TT;
    float arg = (float)t * __expf(-(float)((d >> 1) << 1) * (logf(10000.f) / (float)DD));
    zacc += (d & 1) ? cosf(arg) : sinf(arg);
    z[(size_t)bt * DD + d] = zacc;
}

// ---------------- tf32 tensor-core GEMM (R4-proven version) ----------------
// C = A(MxK) @ B(KxN) + bias. 128x128 block tile, 8 warps (2x4), 64x32 warp tile,
// m16n8k8 tf32 mma, K-step 16, smem stride 136 (conflict-free fragment loads).
// EPI: 0 = bias, 1 = bias+relu, 2 = bias + residual + LayerNorm (N==128 only).
#define TFS 136
template<int EPI>
__global__ void __launch_bounds__(256)
gemm_tf32(const float* __restrict__ A, const float* __restrict__ Bm,
          const float* __restrict__ bias, float* __restrict__ Cm,
          const float* __restrict__ resid,
          const float* __restrict__ ln_g, const float* __restrict__ ln_b,
          int M, int N, int K)
{
    extern __shared__ char smem_raw[];
    uint32_t* As = (uint32_t*)smem_raw;          // [16][TFS]
    uint32_t* Bs = As + 16*TFS;                  // [16][TFS]

    int tid = threadIdx.x;
    int warp = tid >> 5, lane = tid & 31;
    int tig = lane & 3, grp = lane >> 2;
    int wm = warp >> 2, wn = warp & 3;           // 2 x 4 warps
    int m0 = blockIdx.y * 128, n0 = blockIdx.x * 128;

    float acc[4][4][4];
    #pragma unroll
    for (int i = 0; i < 4; i++)
        #pragma unroll
        for (int j = 0; j < 4; j++)
            #pragma unroll
            for (int c = 0; c < 4; c++) acc[i][j][c] = 0.f;

    for (int k0 = 0; k0 < K; k0 += 16) {
        // stage A (transposed to [k][m], tf32)
        #pragma unroll
        for (int l = 0; l < 2; l++) {
            int f = tid + l*256;
            int ma = f >> 2, kc = f & 3;
            float4 v = *(const float4*)&A[(size_t)(m0 + ma)*K + k0 + kc*4];
            As[(kc*4 + 0)*TFS + ma] = to_tf32(v.x);
            As[(kc*4 + 1)*TFS + ma] = to_tf32(v.y);
            As[(kc*4 + 2)*TFS + ma] = to_tf32(v.z);
            As[(kc*4 + 3)*TFS + ma] = to_tf32(v.w);
        }
        // stage B ([k][n], tf32)
        #pragma unroll
        for (int l = 0; l < 2; l++) {
            int f = tid + l*256;
            int kb = f >> 5, nc = f & 31;
            float4 v = *(const float4*)&Bm[(size_t)(k0 + kb)*N + n0 + nc*4];
            uint32_t* p = &Bs[kb*TFS + nc*4];
            p[0] = to_tf32(v.x); p[1] = to_tf32(v.y);
            p[2] = to_tf32(v.z); p[3] = to_tf32(v.w);
        }
        __syncthreads();

        #pragma unroll
        for (int ks = 0; ks < 2; ks++) {
            int kb = ks*8;
            uint32_t afr[4][4];
            #pragma unroll
            for (int mf = 0; mf < 4; mf++) {
                int r0 = wm*64 + mf*16 + grp;
                afr[mf][0] = As[(kb + tig)*TFS + r0];
                afr[mf][1] = As[(kb + tig)*TFS + r0 + 8];
                afr[mf][2] = As[(kb + tig + 4)*TFS + r0];
                afr[mf][3] = As[(kb + tig + 4)*TFS + r0 + 8];
            }
            uint32_t bfr[4][2];
            #pragma unroll
            for (int nf = 0; nf < 4; nf++) {
                int c0 = wn*32 + nf*8 + grp;
                bfr[nf][0] = Bs[(kb + tig)*TFS + c0];
                bfr[nf][1] = Bs[(kb + tig + 4)*TFS + c0];
            }
            #pragma unroll
            for (int mf = 0; mf < 4; mf++)
                #pragma unroll
                for (int nf = 0; nf < 4; nf++)
                    mma_tf32(acc[mf][nf], afr[mf], bfr[nf]);
        }
        __syncthreads();
    }

    if (EPI == 2) {
        // Stage C into smem [128][132], then row-wise residual+LN (N==128, n0==0).
        float* Cs = (float*)smem_raw;            // [128][132]
        #pragma unroll
        for (int mf = 0; mf < 4; mf++) {
            int r = wm*64 + mf*16 + grp;
            #pragma unroll
            for (int nf = 0; nf < 4; nf++) {
                int c = wn*32 + nf*8 + 2*tig;
                Cs[r*132 + c]           = acc[mf][nf][0];
                Cs[r*132 + c + 1]       = acc[mf][nf][1];
                Cs[(r + 8)*132 + c]     = acc[mf][nf][2];
                Cs[(r + 8)*132 + c + 1] = acc[mf][nf][3];
            }
        }
        __syncthreads();

        float4 bb = *(const float4*)&bias[lane*4];
        float4 gg = *(const float4*)&ln_g[lane*4];
        float4 be = *(const float4*)&ln_b[lane*4];
        for (int r = warp*16; r < warp*16 + 16; r++) {
            int m = m0 + r;
            float4 cv = *(const float4*)&Cs[r*132 + lane*4];
            float4 zv = *(const float4*)&resid[(size_t)m*128 + lane*4];
            float v[4] = {cv.x + bb.x + zv.x, cv.y + bb.y + zv.y,
                          cv.z + bb.z + zv.z, cv.w + bb.w + zv.w};
            float s = v[0] + v[1] + v[2] + v[3];
            #pragma unroll
            for (int o = 16; o > 0; o >>= 1) s += __shfl_xor_sync(0xffffffffu, s, o);
            float mu = s * (1.f / 128.f);
            float q = 0.f;
            #pragma unroll
            for (int j = 0; j < 4; j++) { float dv = v[j] - mu; q += dv * dv; }
            #pragma unroll
            for (int o = 16; o > 0; o >>= 1) q += __shfl_xor_sync(0xffffffffu, q, o);
            float rstd = rsqrtf(q * (1.f / 128.f) + 1e-5f);
            float4 rv;
            rv.x = (v[0] - mu) * rstd * gg.x + be.x;
            rv.y = (v[1] - mu) * rstd * gg.y + be.y;
            rv.z = (v[2] - mu) * rstd * gg.z + be.z;
            rv.w = (v[3] - mu) * rstd * gg.w + be.w;
            *(float4*)&Cm[(size_t)m*128 + lane*4] = rv;
        }
    } else {
        #pragma unroll
        for (int mf = 0; mf < 4; mf++) {
            int r = m0 + wm*64 + mf*16 + grp;
            #pragma unroll
            for (int nf = 0; nf < 4; nf++) {
                int c = n0 + wn*32 + nf*8 + 2*tig;
                float b0 = bias[c], b1 = bias[c + 1];
                float v0 = acc[mf][nf][0] + b0;
                float v1 = acc[mf][nf][1] + b1;
                float v2 = acc[mf][nf][2] + b0;
                float v3 = acc[mf][nf][3] + b1;
                if (EPI == 1) {
                    v0 = fmaxf(v0, 0.f); v1 = fmaxf(v1, 0.f);
                    v2 = fmaxf(v2, 0.f); v3 = fmaxf(v3, 0.f);
                }
                *(float2*)&Cm[(size_t)r*N + c]       = make_float2(v0, v1);
                *(float2*)&Cm[(size_t)(r + 8)*N + c] = make_float2(v2, v3);
            }
        }
    }
}

// ---------------- attention per (b, head): R4 math + V-overlap + balance ----
#define QKS 36
#define SSS 76
__global__ void __launch_bounds__(256, 4)
attn_kernel(const float* __restrict__ qkv, float* __restrict__ obuf)
{
    int b = blockIdx.x;
    int h = blockIdx.y;
    int tid = threadIdx.x;  // 256

    __shared__ float sq[TT*QKS];    // Q during S; V afterwards
    __shared__ float sk[TT*QKS];    // K
    __shared__ float sS[TT*SSS];

    const float* base = qkv + (size_t)b * TT * (3*DD) + h*DHEAD;
    for (int idx = tid; idx < TT*DHEAD; idx += 256) {
        int t = idx >> 5, d = idx & 31;
        sq[t*QKS + d] = base[t*(3*DD)      + d];
        sk[t*QKS + d] = base[t*(3*DD) + DD + d];
    }
    __syncthreads();

    const float inv_scale = rsqrtf((float)DHEAD);
    // S = Q @ K^T * inv_scale : 4x4 register tiles, 324 tiles (R4-proven)
    for (int tt = tid; tt < 324; tt += 256) {
        int i0 = (tt / 18) * 4, j0 = (tt % 18) * 4;
        float acc[4][4];
        #pragma unroll
        for (int a = 0; a < 4; a++)
            #pragma unroll
            for (int c = 0; c < 4; c++) acc[a][c] = 0.f;
        #pragma unroll
        for (int d4 = 0; d4 < DHEAD; d4 += 4) {
            float4 q[4], k[4];
            #pragma unroll
            for (int a = 0; a < 4; a++) q[a] = *(const float4*)&sq[(i0+a)*QKS + d4];
            #pragma unroll
            for (int c = 0; c < 4; c++) k[c] = *(const float4*)&sk[(j0+c)*QKS + d4];
            #pragma unroll
            for (int a = 0; a < 4; a++)
                #pragma unroll
                for (int c = 0; c < 4; c++)
                    acc[a][c] += q[a].x*k[c].x + q[a].y*k[c].y + q[a].z*k[c].z + q[a].w*k[c].w;
        }
        #pragma unroll
        for (int a = 0; a < 4; a++)
            #pragma unroll
            for (int c = 0; c < 4; c++)
                sS[(i0+a)*SSS + j0 + c] = acc[a][c] * inv_scale;
    }
    __syncthreads();

    // Load V into sq (Q dead) — overlaps with softmax in the same sync window
    for (int idx = tid; idx < TT*DHEAD; idx += 256) {
        int t = idx >> 5, d = idx & 31;
        sq[t*QKS + d] = base[t*(3*DD) + 2*DD + d];
    }

    // rowwise softmax: warp per row, 8 warps
    int wid = tid >> 5, lane = tid & 31;
    for (int i = wid; i < TT; i += 8) {
        float m = -1e30f;
        for (int j = lane; j < TT; j += 32) m = fmaxf(m, sS[i*SSS + j]);
        #pragma unroll
        for (int o = 16; o > 0; o >>= 1) m = fmaxf(m, __shfl_xor_sync(0xffffffffu, m, o));
        float s = 0.f;
        for (int j = lane; j < TT; j += 32) {
            float e = __expf(sS[i*SSS + j] - m);
            sS[i*SSS + j] = e;
            s += e;
        }
        #pragma unroll
        for (int o = 16; o > 0; o >>= 1) s += __shfl_xor_sync(0xffffffffu, s, o);
        float inv = 1.f / s;
        for (int j = lane; j < TT; j += 32) sS[i*SSS + j] *= inv;
    }
    __syncthreads();

    // O = S @ V : 288 (1 row x 8 col) tiles, plain fp32, all threads active
    for (int tt = tid; tt < 288; tt += 256) {
        int i = tt >> 2;
        int d0 = (tt & 3) * 8;
        float acc[8];
        #pragma unroll
        for (int c = 0; c < 8; c++) acc[c] = 0.f;
        for (int j = 0; j < TT; j++) {
            float s = sS[i*SSS + j];
            float4 v0 = *(const float4*)&sq[j*QKS + d0];
            float4 v1 = *(const float4*)&sq[j*QKS + d0 + 4];
            acc[0] += s*v0.x; acc[1] += s*v0.y; acc[2] += s*v0.z; acc[3] += s*v0.w;
            acc[4] += s*v1.x; acc[5] += s*v1.y; acc[6] += s*v1.z; acc[7] += s*v1.w;
        }
        float* o = &obuf[((size_t)b*TT + i)*DD + h*DHEAD + d0];
        *(float4*)o       = make_float4(acc[0], acc[1], acc[2], acc[3]);
        *(float4*)(o + 4) = make_float4(acc[4], acc[5], acc[6], acc[7]);
    }
}

// ---------------- 6 MLP heads on last timestep ----------------
__global__ void heads_kernel(const float* __restrict__ z,
                             const float* __restrict__ hw1, const float* __restrict__ hb1,
                             const float* __restrict__ hw2, const float* __restrict__ hb2,
                             float* __restrict__ out)
{
    int b = blockIdx.x;
    int k = blockIdx.y;
    int tid = threadIdx.x;  // 64
    __shared__ float slast[DD];
    __shared__ float sh1[64];
    const float* zr = z + ((size_t)b*TT + (TT-1))*DD;
    slast[tid] = zr[tid];
    slast[tid + 64] = zr[tid + 64];
    __syncthreads();

    float acc = hb1[k*64 + tid];
    const float* w1 = hw1 + (size_t)k*DD*64;
    #pragma unroll 8
    for (int d = 0; d < DD; d++) acc += slast[d] * w1[d*64 + tid];
    sh1[tid] = fmaxf(acc, 0.f);
    __syncthreads();

    if (tid < 5) {
        float a2 = hb2[k*5 + tid];
        const float* w2 = hw2 + (size_t)k*64*5;
        #pragma unroll 8
        for (int m = 0; m < 64; m++) a2 += sh1[m] * w2[m*5 + tid];
        out[((size_t)k*BB + b)*5 + tid] = a2;
    }
}

// ---------------- launcher ----------------
extern "C" void kernel_launch(void* const* d_in, const int* in_sizes, int n_in,
                              void* d_out, int out_size)
{
    const float* x        = (const float*)d_in[0];
    const int*   ei       = (const int*)  d_in[1];
    const float* gcn_w    = (const float*)d_in[2];
    const float* gcn_b    = (const float*)d_in[3];
    const float* gat_w    = (const float*)d_in[4];
    const float* gat_a_s  = (const float*)d_in[5];
    const float* gat_a_d  = (const float*)d_in[6];
    const float* gat_b    = (const float*)d_in[7];
    const float* gln_g    = (const float*)d_in[8];
    const float* gln_b    = (const float*)d_in[9];
    const float* tw_qkv   = (const float*)d_in[10];
    const float* tb_qkv   = (const float*)d_in[11];
    const float* tw_o     = (const float*)d_in[12];
    const float* tb_o     = (const float*)d_in[13];
    const float* ln1_g    = (const float*)d_in[14];
    const float* ln1_b    = (const float*)d_in[15];
    const float* w_ff1    = (const float*)d_in[16];
    const float* b_ff1    = (const float*)d_in[17];
    const float* w_ff2    = (const float*)d_in[18];
    const float* b_ff2    = (const float*)d_in[19];
    const float* ln2_g    = (const float*)d_in[20];
    const float* ln2_b    = (const float*)d_in[21];
    const float* hw1      = (const float*)d_in[22];
    const float* hb1      = (const float*)d_in[23];
    const float* hw2      = (const float*)d_in[24];
    const float* hb2      = (const float*)d_in[25];
    float* out = (float*)d_out;

    float *zp, *qkvp, *op, *ffp;
    cudaGetSymbolAddress((void**)&zp,   d_z);
    cudaGetSymbolAddress((void**)&qkvp, d_qkv);
    cudaGetSymbolAddress((void**)&op,   d_o);
    cudaGetSymbolAddress((void**)&ffp,  d_ff);

    const int SMEM_MAIN = 2 * 16 * TFS * 4;       // 17408 B
    const int SMEM_EPI2 = 128 * 132 * 4;          // 67584 B
    cudaFuncSetAttribute(gemm_tf32<2>, cudaFuncAttributeMaxDynamicSharedMemorySize, SMEM_EPI2);

    int E = in_sizes[1] / 2;

    build_graph_kernel<<<1, 32>>>(ei, E);

    gcn_gat_kernel<<<BT, 128>>>(x, gcn_w, gcn_b, gat_w, gat_a_s, gat_a_d,
                                gat_b, gln_g, gln_b, zp, E + NN);

    for (int i = 0; i < 3; i++) {
        // qkv = z @ Wqkv + b      (18432 x 384, K=128)
        gemm_tf32<0><<<dim3((3*DD)/128, BT/128), 256, SMEM_MAIN>>>(
            zp, tw_qkv + (size_t)i*DD*3*DD, tb_qkv + (size_t)i*3*DD, qkvp,
            nullptr, nullptr, nullptr, BT, 3*DD, DD);
        // attention
        attn_kernel<<<dim3(BB, NHEAD), 256>>>(qkvp, op);
        // z = LN(z + o @ Wo + b)  — fused epilogue
        gemm_tf32<2><<<dim3(1, BT/128), 256, SMEM_EPI2>>>(
            op, tw_o + (size_t)i*DD*DD, tb_o + (size_t)i*DD, zp,
            zp, ln1_g + (size_t)i*DD, ln1_b + (size_t)i*DD, BT, DD, DD);
        // ff1 = relu(z @ W1 + b1)
        gemm_tf32<1><<<dim3(FFD/128, BT/128), 256, SMEM_MAIN>>>(
            zp, w_ff1 + (size_t)i*DD*FFD, b_ff1 + (size_t)i*FFD, ffp,
            nullptr, nullptr, nullptr, BT, FFD, DD);
        // z = LN(z + ff1 @ W2 + b2) — fused epilogue (K=256)
        gemm_tf32<2><<<dim3(1, BT/128), 256, SMEM_EPI2>>>(
            ffp, w_ff2 + (size_t)i*FFD*DD, b_ff2 + (size_t)i*DD, zp,
            zp, ln2_g + (size_t)i*DD, ln2_b + (size_t)i*DD, BT, DD, FFD);
    }

    heads_kernel<<<dim3(BB, 6), 64>>>(zp, hw1, hb1, hw2, hb2, out);
}

// round 7
// speedup vs baseline: 1.5270x; 1.0023x over previous
#include <cuda_runtime.h>
#include <math.h>
#include <stdint.h>

// Problem constants (fixed by reference)
#define BB 256
#define TT 72
#define NN 5
#define FF_IN 10
#define HH 4
#define CC 32
#define DD 128
#define FFD 256
#define NHEAD 4
#define DHEAD 32
#define BT (BB*TT)   // 18432

// ---------------- device scratch (no allocations allowed) ----------------
__device__ float d_z[BT*DD];
__device__ float d_qkv[BT*3*DD];
__device__ float d_o[BT*DD];
__device__ float d_ff[BT*FFD];
__device__ float d_Anorm[NN*NN];
__device__ int   d_src2[64];
__device__ int   d_dst2[64];

// ---------------- tf32 helpers ----------------
__device__ __forceinline__ uint32_t to_tf32(float x) {
    uint32_t r;
    asm("cvt.rna.tf32.f32 %0, %1;" : "=r"(r) : "f"(x));
    return r;
}
__device__ __forceinline__ void mma_tf32(float* d, const uint32_t* a, const uint32_t* b) {
    asm volatile(
        "mma.sync.aligned.m16n8k8.row.col.f32.tf32.tf32.f32 "
        "{%0,%1,%2,%3}, {%4,%5,%6,%7}, {%8,%9}, {%0,%1,%2,%3};"
        : "+f"(d[0]), "+f"(d[1]), "+f"(d[2]), "+f"(d[3])
        : "r"(a[0]), "r"(a[1]), "r"(a[2]), "r"(a[3]), "r"(b[0]), "r"(b[1]));
}

// ---------------- graph build (single thread, trivial) ----------------
__global__ void build_graph_kernel(const int* __restrict__ ei, int E) {
    if (threadIdx.x != 0 || blockIdx.x != 0) return;
    float A[NN][NN];
    for (int i = 0; i < NN*NN; i++) ((float*)A)[i] = 0.f;
    for (int e = 0; e < E; e++) {
        int s = ei[e];
        int d = ei[E + e];
        A[d][s] += 1.f;
        d_src2[e] = s; d_dst2[e] = d;
    }
    for (int n = 0; n < NN; n++) {
        A[n][n] += 1.f;
        d_src2[E + n] = n; d_dst2[E + n] = n;
    }
    float dinv[NN];
    for (int n = 0; n < NN; n++) {
        float s = 0.f;
        for (int j = 0; j < NN; j++) s += A[n][j];
        dinv[n] = (s > 0.f) ? (1.f / sqrtf(s)) : 0.f;
    }
    for (int i = 0; i < NN; i++)
        for (int j = 0; j < NN; j++)
            d_Anorm[i*NN + j] = dinv[i] * A[i][j] * dinv[j];
}

// ---------------- fused dual block reduce (128 threads) ----------------
__device__ __forceinline__ void blockReduceSum2_128(float &a, float &b, float* sred) {
    __syncthreads();
    #pragma unroll
    for (int o = 16; o > 0; o >>= 1) {
        a += __shfl_xor_sync(0xffffffffu, a, o);
        b += __shfl_xor_sync(0xffffffffu, b, o);
    }
    if ((threadIdx.x & 31) == 0) {
        int w = threadIdx.x >> 5;
        sred[w] = a; sred[4 + w] = b;
    }
    __syncthreads();
    a = sred[0] + sred[1] + sred[2] + sred[3];
    b = sred[4] + sred[5] + sred[6] + sred[7];
}

// ---------------- fused GCN + GAT + LN + node-mean + PE ----------------
__global__ void gcn_gat_kernel(
    const float* __restrict__ x,
    const float* __restrict__ gcn_w, const float* __restrict__ gcn_b,
    const float* __restrict__ gat_w, const float* __restrict__ a_src,
    const float* __restrict__ a_dst, const float* __restrict__ gat_b,
    const float* __restrict__ gln_g, const float* __restrict__ gln_b,
    float* __restrict__ z, int E2)
{
    int bt = blockIdx.x;
    int tid = threadIdx.x;  // 128

    __shared__ float sx[NN][FF_IN];
    __shared__ float sxw[NN][64];
    __shared__ float sgcn[NN][64];
    __shared__ float sh[NN][DD];
    __shared__ float sagg[NN][DD];
    __shared__ float sas[NN][HH], sad[NN][HH];
    __shared__ float se[32][HH];
    __shared__ float salpha[32][HH];
    __shared__ float smx[NN][HH], sden[NN][HH];
    __shared__ float sAn[NN*NN];
    __shared__ int   ssrc[32], sdst[32];
    __shared__ float sred[8];

    const float* xp = x + (size_t)bt * NN * FF_IN;
    if (tid < NN*FF_IN) ((float*)sx)[tid] = xp[tid];
    if (tid < NN*NN) sAn[tid] = d_Anorm[tid];
    if (tid < E2) { ssrc[tid] = d_src2[tid]; sdst[tid] = d_dst2[tid]; }
    __syncthreads();

    for (int idx = tid; idx < NN*64; idx += 128) {
        int n = idx >> 6, c = idx & 63;
        float acc = gcn_b[c];
        #pragma unroll
        for (int f = 0; f < FF_IN; f++) acc += sx[n][f] * gcn_w[f*64 + c];
        sxw[n][c] = acc;
    }
    __syncthreads();

    for (int idx = tid; idx < NN*64; idx += 128) {
        int n = idx >> 6, c = idx & 63;
        float acc = 0.f;
        #pragma unroll
        for (int m = 0; m < NN; m++) acc += sAn[n*NN + m] * sxw[m][c];
        sgcn[n][c] = tanhf(acc);
    }
    __syncthreads();

    for (int idx = tid; idx < NN*DD; idx += 128) {
        int n = idx >> 7, d = idx & 127;
        float acc = 0.f;
        #pragma unroll 8
        for (int f = 0; f < 64; f++) acc += sgcn[n][f] * gat_w[f*DD + d];
        sh[n][d] = acc;
    }
    __syncthreads();

    if (tid < NN*HH*2) {
        int n = tid / (HH*2), r = tid % (HH*2), hd = r >> 1, which = r & 1;
        const float* av = which ? a_dst : a_src;
        float acc = 0.f;
        #pragma unroll
        for (int c = 0; c < CC; c++) acc += sh[n][hd*CC + c] * av[hd*CC + c];
        if (which) sad[n][hd] = acc; else sas[n][hd] = acc;
    }
    __syncthreads();

    for (int idx = tid; idx < E2*HH; idx += 128) {
        int e = idx >> 2, hd = idx & 3;
        float v = sas[ssrc[e]][hd] + sad[sdst[e]][hd];
        se[e][hd] = (v > 0.f) ? v : 0.2f * v;
    }
    __syncthreads();

    if (tid < NN*HH) {
        int n = tid >> 2, hd = tid & 3;
        float m = -1e30f;
        for (int e = 0; e < E2; e++) if (sdst[e] == n) m = fmaxf(m, se[e][hd]);
        float s = 0.f;
        for (int e = 0; e < E2; e++) if (sdst[e] == n) s += __expf(se[e][hd] - m);
        smx[n][hd] = m; sden[n][hd] = s;
    }
    __syncthreads();

    for (int idx = tid; idx < E2*HH; idx += 128) {
        int e = idx >> 2, hd = idx & 3;
        int n = sdst[e];
        salpha[e][hd] = __expf(se[e][hd] - smx[n][hd]) / sden[n][hd];
    }
    __syncthreads();

    for (int idx = tid; idx < NN*DD; idx += 128) {
        int n = idx >> 7, d = idx & 127;
        int hd = d >> 5;
        float acc = 0.f;
        for (int e = 0; e < E2; e++) {
            if (sdst[e] == n)
                acc += salpha[e][hd] * sh[ssrc[e]][d];
        }
        sagg[n][d] = acc + gat_b[d];
    }

    int d = tid;
    float gv = gln_g[d], bv = gln_b[d];
    float zacc = 0.f;
    for (int n = 0; n < NN; n++) {
        float v = sagg[n][d];
        float s1 = v, s2 = v * v;
        blockReduceSum2_128(s1, s2, sred);
        float mu = s1 * (1.f / DD);
        float var = s2 * (1.f / DD) - mu * mu;
        zacc += (v - mu) * rsqrtf(var + 1e-5f) * gv + bv;
    }
    zacc *= (1.f / NN);

    int t = bt % TT;
    float arg = (float)t * __expf(-(float)((d >> 1) << 1) * (logf(10000.f) / (float)DD));
    zacc += (d & 1) ? cosf(arg) : sinf(arg);
    z[(size_t)bt * DD + d] = zacc;
}

// ---------------- tf32 tensor-core GEMM (R4-proven version) ----------------
// C = A(MxK) @ B(KxN) + bias. 128x128 block tile, 8 warps (2x4), 64x32 warp tile,
// m16n8k8 tf32 mma, K-step 16, smem stride 136 (conflict-free fragment loads).
// EPI: 0 = bias, 1 = bias+relu, 2 = bias + residual + LayerNorm (N==128 only).
#define TFS 136
template<int EPI>
__global__ void __launch_bounds__(256)
gemm_tf32(const float* __restrict__ A, const float* __restrict__ Bm,
          const float* __restrict__ bias, float* __restrict__ Cm,
          const float* __restrict__ resid,
          const float* __restrict__ ln_g, const float* __restrict__ ln_b,
          int M, int N, int K)
{
    extern __shared__ char smem_raw[];
    uint32_t* As = (uint32_t*)smem_raw;          // [16][TFS]
    uint32_t* Bs = As + 16*TFS;                  // [16][TFS]

    int tid = threadIdx.x;
    int warp = tid >> 5, lane = tid & 31;
    int tig = lane & 3, grp = lane >> 2;
    int wm = warp >> 2, wn = warp & 3;           // 2 x 4 warps
    int m0 = blockIdx.y * 128, n0 = blockIdx.x * 128;

    float acc[4][4][4];
    #pragma unroll
    for (int i = 0; i < 4; i++)
        #pragma unroll
        for (int j = 0; j < 4; j++)
            #pragma unroll
            for (int c = 0; c < 4; c++) acc[i][j][c] = 0.f;

    for (int k0 = 0; k0 < K; k0 += 16) {
        // stage A (transposed to [k][m], tf32)
        #pragma unroll
        for (int l = 0; l < 2; l++) {
            int f = tid + l*256;
            int ma = f >> 2, kc = f & 3;
            float4 v = *(const float4*)&A[(size_t)(m0 + ma)*K + k0 + kc*4];
            As[(kc*4 + 0)*TFS + ma] = to_tf32(v.x);
            As[(kc*4 + 1)*TFS + ma] = to_tf32(v.y);
            As[(kc*4 + 2)*TFS + ma] = to_tf32(v.z);
            As[(kc*4 + 3)*TFS + ma] = to_tf32(v.w);
        }
        // stage B ([k][n], tf32)
        #pragma unroll
        for (int l = 0; l < 2; l++) {
            int f = tid + l*256;
            int kb = f >> 5, nc = f & 31;
            float4 v = *(const float4*)&Bm[(size_t)(k0 + kb)*N + n0 + nc*4];
            uint32_t* p = &Bs[kb*TFS + nc*4];
            p[0] = to_tf32(v.x); p[1] = to_tf32(v.y);
            p[2] = to_tf32(v.z); p[3] = to_tf32(v.w);
        }
        __syncthreads();

        #pragma unroll
        for (int ks = 0; ks < 2; ks++) {
            int kb = ks*8;
            uint32_t afr[4][4];
            #pragma unroll
            for (int mf = 0; mf < 4; mf++) {
                int r0 = wm*64 + mf*16 + grp;
                afr[mf][0] = As[(kb + tig)*TFS + r0];
                afr[mf][1] = As[(kb + tig)*TFS + r0 + 8];
                afr[mf][2] = As[(kb + tig + 4)*TFS + r0];
                afr[mf][3] = As[(kb + tig + 4)*TFS + r0 + 8];
            }
            uint32_t bfr[4][2];
            #pragma unroll
            for (int nf = 0; nf < 4; nf++) {
                int c0 = wn*32 + nf*8 + grp;
                bfr[nf][0] = Bs[(kb + tig)*TFS + c0];
                bfr[nf][1] = Bs[(kb + tig + 4)*TFS + c0];
            }
            #pragma unroll
            for (int mf = 0; mf < 4; mf++)
                #pragma unroll
                for (int nf = 0; nf < 4; nf++)
                    mma_tf32(acc[mf][nf], afr[mf], bfr[nf]);
        }
        __syncthreads();
    }

    if (EPI == 2) {
        // Stage C into smem [128][132], then row-wise residual+LN (N==128, n0==0).
        float* Cs = (float*)smem_raw;            // [128][132]
        #pragma unroll
        for (int mf = 0; mf < 4; mf++) {
            int r = wm*64 + mf*16 + grp;
            #pragma unroll
            for (int nf = 0; nf < 4; nf++) {
                int c = wn*32 + nf*8 + 2*tig;
                Cs[r*132 + c]           = acc[mf][nf][0];
                Cs[r*132 + c + 1]       = acc[mf][nf][1];
                Cs[(r + 8)*132 + c]     = acc[mf][nf][2];
                Cs[(r + 8)*132 + c + 1] = acc[mf][nf][3];
            }
        }
        __syncthreads();

        float4 bb = *(const float4*)&bias[lane*4];
        float4 gg = *(const float4*)&ln_g[lane*4];
        float4 be = *(const float4*)&ln_b[lane*4];
        for (int r = warp*16; r < warp*16 + 16; r++) {
            int m = m0 + r;
            float4 cv = *(const float4*)&Cs[r*132 + lane*4];
            float4 zv = *(const float4*)&resid[(size_t)m*128 + lane*4];
            float v[4] = {cv.x + bb.x + zv.x, cv.y + bb.y + zv.y,
                          cv.z + bb.z + zv.z, cv.w + bb.w + zv.w};
            float s = v[0] + v[1] + v[2] + v[3];
            #pragma unroll
            for (int o = 16; o > 0; o >>= 1) s += __shfl_xor_sync(0xffffffffu, s, o);
            float mu = s * (1.f / 128.f);
            float q = 0.f;
            #pragma unroll
            for (int j = 0; j < 4; j++) { float dv = v[j] - mu; q += dv * dv; }
            #pragma unroll
            for (int o = 16; o > 0; o >>= 1) q += __shfl_xor_sync(0xffffffffu, q, o);
            float rstd = rsqrtf(q * (1.f / 128.f) + 1e-5f);
            float4 rv;
            rv.x = (v[0] - mu) * rstd * gg.x + be.x;
            rv.y = (v[1] - mu) * rstd * gg.y + be.y;
            rv.z = (v[2] - mu) * rstd * gg.z + be.z;
            rv.w = (v[3] - mu) * rstd * gg.w + be.w;
            *(float4*)&Cm[(size_t)m*128 + lane*4] = rv;
        }
    } else {
        #pragma unroll
        for (int mf = 0; mf < 4; mf++) {
            int r = m0 + wm*64 + mf*16 + grp;
            #pragma unroll
            for (int nf = 0; nf < 4; nf++) {
                int c = n0 + wn*32 + nf*8 + 2*tig;
                float b0 = bias[c], b1 = bias[c + 1];
                float v0 = acc[mf][nf][0] + b0;
                float v1 = acc[mf][nf][1] + b1;
                float v2 = acc[mf][nf][2] + b0;
                float v3 = acc[mf][nf][3] + b1;
                if (EPI == 1) {
                    v0 = fmaxf(v0, 0.f); v1 = fmaxf(v1, 0.f);
                    v2 = fmaxf(v2, 0.f); v3 = fmaxf(v3, 0.f);
                }
                *(float2*)&Cm[(size_t)r*N + c]       = make_float2(v0, v1);
                *(float2*)&Cm[(size_t)(r + 8)*N + c] = make_float2(v2, v3);
            }
        }
    }
}

// ---------------- attention per (b, head): R4 base + smem-traffic cuts ------
#define QKS 36
#define SSS 76
__global__ void __launch_bounds__(256, 4)
attn_kernel(const float* __restrict__ qkv, float* __restrict__ obuf)
{
    int b = blockIdx.x;
    int h = blockIdx.y;
    int tid = threadIdx.x;  // 256

    __shared__ float sq[TT*QKS];    // Q during S; V afterwards
    __shared__ float sk[TT*QKS];    // K
    __shared__ float sS[TT*SSS];
    __shared__ float sinv[TT];      // per-row 1/sum for deferred normalization

    const float* base = qkv + (size_t)b * TT * (3*DD) + h*DHEAD;
    for (int idx = tid; idx < TT*DHEAD; idx += 256) {
        int t = idx >> 5, d = idx & 31;
        sq[t*QKS + d] = base[t*(3*DD)      + d];
        sk[t*QKS + d] = base[t*(3*DD) + DD + d];
    }
    __syncthreads();

    const float inv_scale = rsqrtf((float)DHEAD);
    // S = Q @ K^T * inv_scale : 4x4 register tiles, 324 tiles (R4-proven)
    for (int tt = tid; tt < 324; tt += 256) {
        int i0 = (tt / 18) * 4, j0 = (tt % 18) * 4;
        float acc[4][4];
        #pragma unroll
        for (int a = 0; a < 4; a++)
            #pragma unroll
            for (int c = 0; c < 4; c++) acc[a][c] = 0.f;
        #pragma unroll
        for (int d4 = 0; d4 < DHEAD; d4 += 4) {
            float4 q[4], k[4];
            #pragma unroll
            for (int a = 0; a < 4; a++) q[a] = *(const float4*)&sq[(i0+a)*QKS + d4];
            #pragma unroll
            for (int c = 0; c < 4; c++) k[c] = *(const float4*)&sk[(j0+c)*QKS + d4];
            #pragma unroll
            for (int a = 0; a < 4; a++)
                #pragma unroll
                for (int c = 0; c < 4; c++)
                    acc[a][c] += q[a].x*k[c].x + q[a].y*k[c].y + q[a].z*k[c].z + q[a].w*k[c].w;
        }
        #pragma unroll
        for (int a = 0; a < 4; a++)
            #pragma unroll
            for (int c = 0; c < 4; c++)
                sS[(i0+a)*SSS + j0 + c] = acc[a][c] * inv_scale;
    }
    __syncthreads();

    // single-pass register softmax (unnormalized exp stored, 1/sum deferred)
    int wid = tid >> 5, lane = tid & 31;
    for (int i = wid; i < TT; i += 8) {
        float v0 = sS[i*SSS + lane];
        float v1 = sS[i*SSS + lane + 32];
        float v2 = (lane < 8) ? sS[i*SSS + lane + 64] : -1e30f;
        float m = fmaxf(fmaxf(v0, v1), v2);
        #pragma unroll
        for (int o = 16; o > 0; o >>= 1) m = fmaxf(m, __shfl_xor_sync(0xffffffffu, m, o));
        float e0 = __expf(v0 - m);
        float e1 = __expf(v1 - m);
        float e2 = (lane < 8) ? __expf(v2 - m) : 0.f;
        sS[i*SSS + lane]      = e0;
        sS[i*SSS + lane + 32] = e1;
        if (lane < 8) sS[i*SSS + lane + 64] = e2;
        float s = e0 + e1 + e2;
        #pragma unroll
        for (int o = 16; o > 0; o >>= 1) s += __shfl_xor_sync(0xffffffffu, s, o);
        if (lane == 0) sinv[i] = 1.f / s;
    }
    __syncthreads();

    // Load V into sq (Q dead); own sync window (R6 showed overlap hurts)
    for (int idx = tid; idx < TT*DHEAD; idx += 256) {
        int t = idx >> 5, d = idx & 31;
        sq[t*QKS + d] = base[t*(3*DD) + 2*DD + d];
    }
    __syncthreads();

    // O = (Sexp @ V) * sinv[i] : 288 (1 row x 8 col) tiles, float4 S reads
    for (int tt = tid; tt < 288; tt += 256) {
        int i = tt >> 2;
        int d0 = (tt & 3) * 8;
        float acc[8];
        #pragma unroll
        for (int c = 0; c < 8; c++) acc[c] = 0.f;
        for (int j = 0; j < TT; j += 4) {
            float4 sv = *(const float4*)&sS[i*SSS + j];   // broadcast across d0-threads
            float ss[4] = {sv.x, sv.y, sv.z, sv.w};
            #pragma unroll
            for (int u = 0; u < 4; u++) {
                float s = ss[u];
                float4 v0 = *(const float4*)&sq[(j+u)*QKS + d0];
                float4 v1 = *(const float4*)&sq[(j+u)*QKS + d0 + 4];
                acc[0] += s*v0.x; acc[1] += s*v0.y; acc[2] += s*v0.z; acc[3] += s*v0.w;
                acc[4] += s*v1.x; acc[5] += s*v1.y; acc[6] += s*v1.z; acc[7] += s*v1.w;
            }
        }
        float inv = sinv[i];
        #pragma unroll
        for (int c = 0; c < 8; c++) acc[c] *= inv;
        float* o = &obuf[((size_t)b*TT + i)*DD + h*DHEAD + d0];
        *(float4*)o       = make_float4(acc[0], acc[1], acc[2], acc[3]);
        *(float4*)(o + 4) = make_float4(acc[4], acc[5], acc[6], acc[7]);
    }
}

// ---------------- 6 MLP heads on last timestep ----------------
__global__ void heads_kernel(const float* __restrict__ z,
                             const float* __restrict__ hw1, const float* __restrict__ hb1,
                             const float* __restrict__ hw2, const float* __restrict__ hb2,
                             float* __restrict__ out)
{
    int b = blockIdx.x;
    int k = blockIdx.y;
    int tid = threadIdx.x;  // 64
    __shared__ float slast[DD];
    __shared__ float sh1[64];
    const float* zr = z + ((size_t)b*TT + (TT-1))*DD;
    slast[tid] = zr[tid];
    slast[tid + 64] = zr[tid + 64];
    __syncthreads();

    float acc = hb1[k*64 + tid];
    const float* w1 = hw1 + (size_t)k*DD*64;
    #pragma unroll 8
    for (int d = 0; d < DD; d++) acc += slast[d] * w1[d*64 + tid];
    sh1[tid] = fmaxf(acc, 0.f);
    __syncthreads();

    if (tid < 5) {
        float a2 = hb2[k*5 + tid];
        const float* w2 = hw2 + (size_t)k*64*5;
        #pragma unroll 8
        for (int m = 0; m < 64; m++) a2 += sh1[m] * w2[m*5 + tid];
        out[((size_t)k*BB + b)*5 + tid] = a2;
    }
}

// ---------------- launcher ----------------
extern "C" void kernel_launch(void* const* d_in, const int* in_sizes, int n_in,
                              void* d_out, int out_size)
{
    const float* x        = (const float*)d_in[0];
    const int*   ei       = (const int*)  d_in[1];
    const float* gcn_w    = (const float*)d_in[2];
    const float* gcn_b    = (const float*)d_in[3];
    const float* gat_w    = (const float*)d_in[4];
    const float* gat_a_s  = (const float*)d_in[5];
    const float* gat_a_d  = (const float*)d_in[6];
    const float* gat_b    = (const float*)d_in[7];
    const float* gln_g    = (const float*)d_in[8];
    const float* gln_b    = (const float*)d_in[9];
    const float* tw_qkv   = (const float*)d_in[10];
    const float* tb_qkv   = (const float*)d_in[11];
    const float* tw_o     = (const float*)d_in[12];
    const float* tb_o     = (const float*)d_in[13];
    const float* ln1_g    = (const float*)d_in[14];
    const float* ln1_b    = (const float*)d_in[15];
    const float* w_ff1    = (const float*)d_in[16];
    const float* b_ff1    = (const float*)d_in[17];
    const float* w_ff2    = (const float*)d_in[18];
    const float* b_ff2    = (const float*)d_in[19];
    const float* ln2_g    = (const float*)d_in[20];
    const float* ln2_b    = (const float*)d_in[21];
    const float* hw1      = (const float*)d_in[22];
    const float* hb1      = (const float*)d_in[23];
    const float* hw2      = (const float*)d_in[24];
    const float* hb2      = (const float*)d_in[25];
    float* out = (float*)d_out;

    float *zp, *qkvp, *op, *ffp;
    cudaGetSymbolAddress((void**)&zp,   d_z);
    cudaGetSymbolAddress((void**)&qkvp, d_qkv);
    cudaGetSymbolAddress((void**)&op,   d_o);
    cudaGetSymbolAddress((void**)&ffp,  d_ff);

    const int SMEM_MAIN = 2 * 16 * TFS * 4;       // 17408 B
    const int SMEM_EPI2 = 128 * 132 * 4;          // 67584 B
    cudaFuncSetAttribute(gemm_tf32<2>, cudaFuncAttributeMaxDynamicSharedMemorySize, SMEM_EPI2);

    int E = in_sizes[1] / 2;

    build_graph_kernel<<<1, 32>>>(ei, E);

    gcn_gat_kernel<<<BT, 128>>>(x, gcn_w, gcn_b, gat_w, gat_a_s, gat_a_d,
                                gat_b, gln_g, gln_b, zp, E + NN);

    for (int i = 0; i < 3; i++) {
        // qkv = z @ Wqkv + b      (18432 x 384, K=128)
        gemm_tf32<0><<<dim3((3*DD)/128, BT/128), 256, SMEM_MAIN>>>(
            zp, tw_qkv + (size_t)i*DD*3*DD, tb_qkv + (size_t)i*3*DD, qkvp,
            nullptr, nullptr, nullptr, BT, 3*DD, DD);
        // attention
        attn_kernel<<<dim3(BB, NHEAD), 256>>>(qkvp, op);
        // z = LN(z + o @ Wo + b)  — fused epilogue
        gemm_tf32<2><<<dim3(1, BT/128), 256, SMEM_EPI2>>>(
            op, tw_o + (size_t)i*DD*DD, tb_o + (size_t)i*DD, zp,
            zp, ln1_g + (size_t)i*DD, ln1_b + (size_t)i*DD, BT, DD, DD);
        // ff1 = relu(z @ W1 + b1)
        gemm_tf32<1><<<dim3(FFD/128, BT/128), 256, SMEM_MAIN>>>(
            zp, w_ff1 + (size_t)i*DD*FFD, b_ff1 + (size_t)i*FFD, ffp,
            nullptr, nullptr, nullptr, BT, FFD, DD);
        // z = LN(z + ff1 @ W2 + b2) — fused epilogue (K=256)
        gemm_tf32<2><<<dim3(1, BT/128), 256, SMEM_EPI2>>>(
            ffp, w_ff2 + (size_t)i*FFD*DD, b_ff2 + (size_t)i*DD, zp,
            zp, ln2_g + (size_t)i*DD, ln2_b + (size_t)i*DD, BT, DD, FFD);
    }

    heads_kernel<<<dim3(BB, 6), 64>>>(zp, hw1, hb1, hw2, hb2, out);
}